// round 13
// baseline (speedup 1.0000x reference)
#include <cuda_runtime.h>
#include <cstdint>
#include <math_constants.h>

// OpeningLoss2D: mean((x - grey_opening_2x2(x))^2) over [8,16,512,512] fp32.
// Separable hmin2 -> vmin2 -> hmax2 -> vmax2 (scipy w=2, edge replicate,
// er-index clamps on dilation).
//
// R12 base + paired steps: RING=14 slots (29.1KB, 7 blocks/SM = grid limit),
// 2-row cp.async groups, ONE wait+barrier per 4 rows (17 syncs/tile vs 33).
// float4 smem reads, shuffle halo + predicated lane-0/31 reads, col-512 -inf
// sentinel, interior clamp-free specialization.

#define FULLMASK 0xffffffffu

static const int Hc = 512;
static const int Wc = 512;
static const int TR = 64;
static const int NBLK = 1024;          // 128 slices * 8 row-tiles
static const int ROWP = 520;           // slot stride (floats), 16B aligned
static const int RING = 14;            // 14 slots = 29.12 KB

__device__ float g_partials[NBLK];
__device__ unsigned int g_count = 0;

__device__ __forceinline__ void cp_async16(uint32_t saddr, const float* gaddr) {
    asm volatile("cp.async.cg.shared.global [%0], [%1], 16;\n"
                 :: "r"(saddr), "l"(gaddr));
}
__device__ __forceinline__ void cp_commit() {
    asm volatile("cp.async.commit_group;\n" ::: "memory");
}
template <int N>
__device__ __forceinline__ void cp_wait() {
    asm volatile("cp.async.wait_group %0;\n" :: "n"(N) : "memory");
}

// One 512x64 tile; returns this thread's squared-error partial.
// INTERIOR: r0 in [64,384] -> no row clamps (max overrun row index 75:
// r0-1+75 <= 458 < 512).
template <bool INTERIOR>
__device__ __forceinline__ float process_tile(
    const float* __restrict__ S, float (*ring)[ROWP], uint32_t sring,
    int r0, int c0, bool isL0, bool isL31, int lcol, int rcol)
{
    const float* gp = S + (size_t)(INTERIOR ? (r0 - 1) : 0) * Wc + c0;

    // issue rows p0, p0+1 into slots sl, sl+1 (sl even => no wrap) + commit
    #define ISSUE2(p0, sl) do {                                               \
        if (INTERIOR) {                                                       \
            cp_async16(sring + (uint32_t)((sl)     * (ROWP * 4)),             \
                       gp + (size_t)(p0) * Wc);                               \
            cp_async16(sring + (uint32_t)(((sl)+1) * (ROWP * 4)),             \
                       gp + (size_t)((p0) + 1) * Wc);                         \
        } else {                                                              \
            int _g0 = min(max(r0 - 1 + (p0), 0), Hc - 1);                     \
            int _g1 = min(r0 + (p0), Hc - 1);                                 \
            cp_async16(sring + (uint32_t)((sl)     * (ROWP * 4)),             \
                       S + (size_t)_g0 * Wc + c0);                            \
            cp_async16(sring + (uint32_t)(((sl)+1) * (ROWP * 4)),             \
                       S + (size_t)_g1 * Wc + c0);                            \
        }                                                                     \
        cp_commit();                                                          \
    } while (0)

    #define LOADROW(sl)                                                       \
        const float* _row = &ring[(sl)][0];                                   \
        float4 _q = *reinterpret_cast<const float4*>(_row + c0);              \
        float _L = __shfl_up_sync(FULLMASK, _q.w, 1);                         \
        float _R = __shfl_down_sync(FULLMASK, _q.x, 1);                       \
        if (isL0)  _L = _row[lcol];                                           \
        if (isL31) _R = _row[rcol];                                           \
        float _h0 = fminf(_L,  _q.x), _h1 = fminf(_q.x, _q.y);                \
        float _h2 = fminf(_q.y, _q.z), _h3 = fminf(_q.z, _q.w);               \
        float _h4 = fminf(_q.w, _R);

    #define FULLROW(sl) do {                                                  \
        LOADROW(sl)                                                            \
        float _e0 = fminf(hp0,_h0), _e1 = fminf(hp1,_h1), _e2 = fminf(hp2,_h2);\
        float _e3 = fminf(hp3,_h3), _e4 = fminf(hp4,_h4);                      \
        float _M0 = fmaxf(_e0,_e1), _M1 = fmaxf(_e1,_e2);                      \
        float _M2 = fmaxf(_e2,_e3), _M3 = fmaxf(_e3,_e4);                      \
        float _s0 = fmaxf(Mp0,_M0), _s1 = fmaxf(Mp1,_M1);                      \
        float _s2 = fmaxf(Mp2,_M2), _s3 = fmaxf(Mp3,_M3);                      \
        float _d0 = xp0 - _s0, _d1 = xp1 - _s1;                                \
        float _d2 = xp2 - _s2, _d3 = xp3 - _s3;                                \
        acc0 = fmaf(_d0,_d0,acc0); acc1 = fmaf(_d1,_d1,acc1);                  \
        acc0 = fmaf(_d2,_d2,acc0); acc1 = fmaf(_d3,_d3,acc1);                  \
        hp0=_h0; hp1=_h1; hp2=_h2; hp3=_h3; hp4=_h4;                           \
        Mp0=_M0; Mp1=_M1; Mp2=_M2; Mp3=_M3;                                    \
        xp0=_q.x; xp1=_q.y; xp2=_q.z; xp3=_q.w;                                \
    } while (0)

    float hp0, hp1, hp2, hp3, hp4;
    float Mp0, Mp1, Mp2, Mp3;
    float xp0, xp1, xp2, xp3;
    float acc0 = 0.f, acc1 = 0.f;

    // prologue: groups 0..4 = rows 0..9 -> slots 0..9
    ISSUE2(0, 0); ISSUE2(2, 2); ISSUE2(4, 4); ISSUE2(6, 6); ISSUE2(8, 8);

    // step 0 (rows 0,1) peeled: no er at p=0, no smooth at p=1.
    // Also issue groups 5,6 (rows 10..13 -> slots 10..13).
    cp_wait<4>();
    __syncthreads();
    ISSUE2(10, 10);
    ISSUE2(12, 12);
    {   LOADROW(0)
        hp0=_h0; hp1=_h1; hp2=_h2; hp3=_h3; hp4=_h4;
    }
    {   LOADROW(1)
        float _e0 = fminf(hp0,_h0), _e1 = fminf(hp1,_h1), _e2 = fminf(hp2,_h2);
        float _e3 = fminf(hp3,_h3), _e4 = fminf(hp4,_h4);
        Mp0 = fmaxf(_e0,_e1); Mp1 = fmaxf(_e1,_e2);
        Mp2 = fmaxf(_e2,_e3); Mp3 = fmaxf(_e3,_e4);
        hp0=_h0; hp1=_h1; hp2=_h2; hp3=_h3; hp4=_h4;
        xp0=_q.x; xp1=_q.y; xp2=_q.z; xp3=_q.w;
    }

    // pairs k=1..15: rows 4k-2..4k+1 (read slots rs..), issue rows
    // 4k+10..4k+13 (write slots ws.. = slots read at pair k-1, barrier-safe).
    // Before pair k: 2k+5 groups committed; wait<4> completes through group
    // 2k -> rows <= 4k+1 present and (after barrier) visible to all threads.
    int rs = 2, ws = 0;
    #pragma unroll 7
    for (int k = 1; k <= 15; ++k) {
        cp_wait<4>();
        __syncthreads();
        const int rs2 = (rs + 2 == RING) ? 0 : rs + 2;
        const int ws2 = (ws + 2 == RING) ? 0 : ws + 2;
        ISSUE2(4 * k + 10, ws);
        ISSUE2(4 * k + 12, ws2);
        FULLROW(rs);
        FULLROW(rs + 1);
        FULLROW(rs2);
        FULLROW(rs2 + 1);
        rs = (rs2 + 2 == RING) ? 0 : rs2 + 2;
        ws = (ws2 + 2 == RING) ? 0 : ws2 + 2;
    }

    // tail: rows 62,63 (slots 6,7), then bottom boundary rows 64,65 (slots 8,9)
    cp_wait<0>();
    __syncthreads();
    FULLROW(6);
    FULLROW(7);
    FULLROW(8);
    if (INTERIOR || r0 + TR < Hc) {
        FULLROW(9);
    } else {
        // er row 512 doesn't exist: smooth(511) = hM(511) = Mp
        float _d0 = xp0 - Mp0, _d1 = xp1 - Mp1;
        float _d2 = xp2 - Mp2, _d3 = xp3 - Mp3;
        acc0 = fmaf(_d0,_d0,acc0); acc1 = fmaf(_d1,_d1,acc1);
        acc0 = fmaf(_d2,_d2,acc0); acc1 = fmaf(_d3,_d3,acc1);
    }
    #undef ISSUE2
    #undef LOADROW
    #undef FULLROW

    return acc0 + acc1;
}

__global__ void __launch_bounds__(128, 7)
opening_kernel(const float* __restrict__ X, float* __restrict__ out) {
    __shared__ float ring[RING][ROWP];    // 29.1 KB; data [0..511], sentinel 512
    __shared__ float wsum[4];
    __shared__ bool amLast;

    const int t      = threadIdx.x;       // 0..127
    const int lane   = t & 31;
    const int warpId = t >> 5;
    const int tile   = blockIdx.x;        // 0..1023
    const int slice  = tile >> 3;         // 0..127
    const int r0     = (tile & 7) * TR;
    const float* S   = X + (size_t)slice * (Hc * Wc);
    const int c0     = t << 2;            // first owned column (0..508)
    const bool isL0  = (lane == 0);
    const bool isL31 = (lane == 31);
    const int lcol   = max(c0 - 1, 0);    // left clamp (t=0 -> col 0)
    const int rcol   = c0 + 4;            // t=127 -> col 512 = -inf sentinel

    if (t < RING) ring[t][512] = -CUDART_INF_F;

    const uint32_t sring =
        (uint32_t)__cvta_generic_to_shared(&ring[0][0]) + (uint32_t)(c0 * 4);

    const bool interior = (r0 != 0) && (r0 != (Hc - TR));
    float acc = interior
        ? process_tile<true >(S, ring, sring, r0, c0, isL0, isL31, lcol, rcol)
        : process_tile<false>(S, ring, sring, r0, c0, isL0, isL31, lcol, rcol);

    #pragma unroll
    for (int off = 16; off; off >>= 1)
        acc += __shfl_down_sync(FULLMASK, acc, off);
    if (lane == 0) wsum[warpId] = acc;
    __syncthreads();
    if (t == 0) {
        float s = wsum[0] + wsum[1] + wsum[2] + wsum[3];
        g_partials[blockIdx.x] = s;
        __threadfence();
        unsigned int old = atomicAdd(&g_count, 1u);
        amLast = (old == (unsigned)(NBLK - 1));
    }
    __syncthreads();

    if (amLast) {
        __shared__ float sh[128];
        float s = 0.f;
        for (int i = t; i < NBLK; i += 128) s += g_partials[i];
        sh[t] = s;
        __syncthreads();
        #pragma unroll
        for (int off = 64; off; off >>= 1) {
            if (t < off) sh[t] += sh[t + off];
            __syncthreads();
        }
        if (t == 0) {
            out[0] = sh[0] * (1.0f / 33554432.0f);  // mean over 8*16*512*512
            g_count = 0;                            // deterministic replays
        }
    }
}

extern "C" void kernel_launch(void* const* d_in, const int* in_sizes, int n_in,
                              void* d_out, int out_size) {
    const float* X = (const float*)d_in[0];
    opening_kernel<<<NBLK, 128>>>(X, (float*)d_out);
}

// round 14
// speedup vs baseline: 1.0350x; 1.0350x over previous
#include <cuda_runtime.h>
#include <cstdint>
#include <math_constants.h>

// OpeningLoss2D: mean((x - grey_opening_2x2(x))^2) over [8,16,512,512] fp32.
// Separable hmin2 -> vmin2 -> hmax2 -> vmax2 (scipy w=2, edge replicate,
// er-index clamps on dilation).
//
// 1024 blocks x 128 threads, 512x64 tiles. cp.async ring: 12 slots (25KB),
// 2-row groups, DEPTH 5 (10 rows in flight). Hot loop = super-iterations of
// 6 steps (slot pattern period mod 12) -> all slot offsets immediate, one
// running gmem pointer. Rows 12..59 need no clamps for ANY tile; issues stop
// at row 65 exactly (no overrun traffic) via peeled wait-countdown tail.
// Row p <-> slot p%12 throughout.

#define FULLMASK 0xffffffffu

static const int Hc = 512;
static const int Wc = 512;
static const int TR = 64;
static const int NBLK = 1024;          // 128 slices * 8 row-tiles
static const int ROWP = 520;           // slot stride (floats), 16B aligned
static const int RING = 12;            // 24.96 KB

__device__ float g_partials[NBLK];
__device__ unsigned int g_count = 0;

__device__ __forceinline__ void cp_async16(uint32_t saddr, const float* gaddr) {
    asm volatile("cp.async.cg.shared.global [%0], [%1], 16;\n"
                 :: "r"(saddr), "l"(gaddr));
}
__device__ __forceinline__ void cp_commit() {
    asm volatile("cp.async.commit_group;\n" ::: "memory");
}
template <int N>
__device__ __forceinline__ void cp_wait() {
    asm volatile("cp.async.wait_group %0;\n" :: "n"(N) : "memory");
}

__global__ void __launch_bounds__(128, 9)
opening_kernel(const float* __restrict__ X, float* __restrict__ out) {
    __shared__ float ring[RING][ROWP];    // data [0..511], sentinel at [512]
    __shared__ float wsum[4];
    __shared__ bool amLast;

    const int t      = threadIdx.x;       // 0..127
    const int lane   = t & 31;
    const int warpId = t >> 5;
    const int tile   = blockIdx.x;        // 0..1023
    const int slice  = tile >> 3;         // 0..127
    const int r0     = (tile & 7) * TR;
    const float* S   = X + (size_t)slice * (Hc * Wc);
    const int c0     = t << 2;            // first owned column (0..508)
    const bool isL0  = (lane == 0);
    const bool isL31 = (lane == 31);
    const int lcol   = max(c0 - 1, 0);    // left clamp (t=0 -> col 0)
    const int rcol   = c0 + 4;            // t=127 -> col 512 = -inf sentinel

    if (t < RING) ring[t][512] = -CUDART_INF_F;

    const uint32_t sring =
        (uint32_t)__cvta_generic_to_shared(&ring[0][0]) + (uint32_t)(c0 * 4);

    #define LOADROW(sl)                                                       \
        const float* _row = &ring[(sl)][0];                                   \
        float4 _q = *reinterpret_cast<const float4*>(_row + c0);              \
        float _L = __shfl_up_sync(FULLMASK, _q.w, 1);                         \
        float _R = __shfl_down_sync(FULLMASK, _q.x, 1);                       \
        if (isL0)  _L = _row[lcol];                                           \
        if (isL31) _R = _row[rcol];                                           \
        float _h0 = fminf(_L,  _q.x), _h1 = fminf(_q.x, _q.y);                \
        float _h2 = fminf(_q.y, _q.z), _h3 = fminf(_q.z, _q.w);               \
        float _h4 = fminf(_q.w, _R);

    #define FULLROW(sl) do {                                                  \
        LOADROW(sl)                                                            \
        float _e0 = fminf(hp0,_h0), _e1 = fminf(hp1,_h1), _e2 = fminf(hp2,_h2);\
        float _e3 = fminf(hp3,_h3), _e4 = fminf(hp4,_h4);                      \
        float _M0 = fmaxf(_e0,_e1), _M1 = fmaxf(_e1,_e2);                      \
        float _M2 = fmaxf(_e2,_e3), _M3 = fmaxf(_e3,_e4);                      \
        float _s0 = fmaxf(Mp0,_M0), _s1 = fmaxf(Mp1,_M1);                      \
        float _s2 = fmaxf(Mp2,_M2), _s3 = fmaxf(Mp3,_M3);                      \
        float _d0 = xp0 - _s0, _d1 = xp1 - _s1;                                \
        float _d2 = xp2 - _s2, _d3 = xp3 - _s3;                                \
        acc0 = fmaf(_d0,_d0,acc0); acc1 = fmaf(_d1,_d1,acc1);                  \
        acc0 = fmaf(_d2,_d2,acc0); acc1 = fmaf(_d3,_d3,acc1);                  \
        hp0=_h0; hp1=_h1; hp2=_h2; hp3=_h3; hp4=_h4;                           \
        Mp0=_M0; Mp1=_M1; Mp2=_M2; Mp3=_M3;                                    \
        xp0=_q.x; xp1=_q.y; xp2=_q.z; xp3=_q.w;                                \
    } while (0)

    float hp0, hp1, hp2, hp3, hp4;
    float Mp0, Mp1, Mp2, Mp3;
    float xp0, xp1, xp2, xp3;
    float acc0 = 0.f, acc1 = 0.f;

    // ---- prologue: rows 0..9 -> slots 0..9 (5 groups). Row p = x row
    // clamp(r0-1+p); only p=0 can clamp low; p<=9 never clamps high.
    #define ISSUEP(p) cp_async16(sring + (uint32_t)((p) * (ROWP * 4)),        \
                                 S + (size_t)max(r0 - 1 + (p), 0) * Wc + c0)
    ISSUEP(0); ISSUEP(1); cp_commit();
    ISSUEP(2); ISSUEP(3); cp_commit();
    ISSUEP(4); ISSUEP(5); cp_commit();
    ISSUEP(6); ISSUEP(7); cp_commit();
    ISSUEP(8); ISSUEP(9); cp_commit();

    // ---- step 0 (rows 0,1): issue rows 10,11 -> slots 10,11 (group 5)
    cp_wait<4>();
    __syncthreads();
    ISSUEP(10); ISSUEP(11); cp_commit();
    #undef ISSUEP
    {   LOADROW(0)
        hp0=_h0; hp1=_h1; hp2=_h2; hp3=_h3; hp4=_h4;
    }
    {   LOADROW(1)
        float _e0 = fminf(hp0,_h0), _e1 = fminf(hp1,_h1), _e2 = fminf(hp2,_h2);
        float _e3 = fminf(hp3,_h3), _e4 = fminf(hp4,_h4);
        Mp0 = fmaxf(_e0,_e1); Mp1 = fmaxf(_e1,_e2);
        Mp2 = fmaxf(_e2,_e3); Mp3 = fmaxf(_e3,_e4);
        hp0=_h0; hp1=_h1; hp2=_h2; hp3=_h3; hp4=_h4;
        xp0=_q.x; xp1=_q.y; xp2=_q.z; xp3=_q.w;
    }

    // ---- hot loop: steps 1..24 in 4 super-iterations of 6. Step s reads
    // rows 2s,2s+1 (slots (2s)%12) and issues rows 2s+10,2s+11 into the slots
    // read at step s-1 (barrier-ordered). Issued rows 12..59 -> x rows
    // r0+11..r0+58, in-bounds for every tile (r0<=448 -> <=506): no clamps.
    // Wait math: before step s, committed = s+5 groups; need s+1 complete;
    // wait<4> leaves <=4 incomplete. OK for s=1..24.
    #define HOT(KOFF, RS, WS) do {                                            \
        cp_wait<4>();                                                         \
        __syncthreads();                                                      \
        cp_async16(sring + (uint32_t)((WS)     * (ROWP * 4)),                 \
                   gq + (size_t)(KOFF) * Wc);                                 \
        cp_async16(sring + (uint32_t)(((WS)+1) * (ROWP * 4)),                 \
                   gq + (size_t)((KOFF)+1) * Wc);                             \
        cp_commit();                                                          \
        FULLROW(RS);                                                          \
        FULLROW((RS)+1);                                                      \
    } while (0)

    const float* gq = S + (size_t)(r0 + 11) * Wc + c0;   // row 12 of pipeline
    #pragma unroll 1
    for (int i = 0; i < 4; ++i) {
        HOT(0, 2, 0);     // s = 6i+1
        HOT(2, 4, 2);     // s = 6i+2
        HOT(4, 6, 4);     // s = 6i+3
        HOT(6, 8, 6);     // s = 6i+4
        HOT(8, 10, 8);    // s = 6i+5
        HOT(10, 0, 10);   // s = 6i+6
        gq += 12 * Wc;
    }
    #undef HOT

    // ---- peeled steps 25..27: issue the last rows 60..65 (clamped high for
    // the bottom tile: r0=448 -> x rows up to 512 -> min to 511).
    #define PEELI(p0, WS) do {                                                \
        int _g0 = min(r0 - 1 + (p0), Hc - 1);                                 \
        int _g1 = min(r0 + (p0), Hc - 1);                                     \
        cp_async16(sring + (uint32_t)((WS)     * (ROWP * 4)),                 \
                   S + (size_t)_g0 * Wc + c0);                                \
        cp_async16(sring + (uint32_t)(((WS)+1) * (ROWP * 4)),                 \
                   S + (size_t)_g1 * Wc + c0);                                \
        cp_commit();                                                          \
    } while (0)

    // s=25: reads rows 50,51 (slots 2,3); issues rows 60,61 -> slots 0,1
    cp_wait<4>(); __syncthreads(); PEELI(60, 0); FULLROW(2); FULLROW(3);
    // s=26: rows 52,53 (slots 4,5); issues rows 62,63 -> slots 2,3
    cp_wait<4>(); __syncthreads(); PEELI(62, 2); FULLROW(4); FULLROW(5);
    // s=27: rows 54,55 (slots 6,7); issues rows 64,65 -> slots 4,5
    cp_wait<4>(); __syncthreads(); PEELI(64, 4); FULLROW(6); FULLROW(7);
    #undef PEELI
    // All 33 groups committed (rows 0..65, zero overrun). Countdown waits:
    // s=28: rows 56,57 (slots 8,9); need 29 complete = 33-4
    cp_wait<4>(); __syncthreads(); FULLROW(8); FULLROW(9);
    // s=29: rows 58,59 (slots 10,11); need 30 = 33-3
    cp_wait<3>(); __syncthreads(); FULLROW(10); FULLROW(11);
    // s=30: rows 60,61 (slots 0,1); need 31 = 33-2
    cp_wait<2>(); __syncthreads(); FULLROW(0); FULLROW(1);
    // s=31: rows 62,63 (slots 2,3); need 32 = 33-1
    cp_wait<1>(); __syncthreads(); FULLROW(2); FULLROW(3);
    // tail: rows 64,65 (slots 4,5)
    cp_wait<0>(); __syncthreads();
    FULLROW(4);
    if (r0 + TR >= Hc) {
        // er row 512 doesn't exist: smooth(511) = hM(511) = Mp
        float _d0 = xp0 - Mp0, _d1 = xp1 - Mp1;
        float _d2 = xp2 - Mp2, _d3 = xp3 - Mp3;
        acc0 = fmaf(_d0,_d0,acc0); acc1 = fmaf(_d1,_d1,acc1);
        acc0 = fmaf(_d2,_d2,acc0); acc1 = fmaf(_d3,_d3,acc1);
    } else {
        FULLROW(5);
    }
    #undef LOADROW
    #undef FULLROW

    float acc = acc0 + acc1;
    #pragma unroll
    for (int off = 16; off; off >>= 1)
        acc += __shfl_down_sync(FULLMASK, acc, off);
    if (lane == 0) wsum[warpId] = acc;
    __syncthreads();
    if (t == 0) {
        float s = wsum[0] + wsum[1] + wsum[2] + wsum[3];
        g_partials[blockIdx.x] = s;
        __threadfence();
        unsigned int old = atomicAdd(&g_count, 1u);
        amLast = (old == (unsigned)(NBLK - 1));
    }
    __syncthreads();

    if (amLast) {
        __shared__ float sh[128];
        float s = 0.f;
        for (int i = t; i < NBLK; i += 128) s += g_partials[i];
        sh[t] = s;
        __syncthreads();
        #pragma unroll
        for (int off = 64; off; off >>= 1) {
            if (t < off) sh[t] += sh[t + off];
            __syncthreads();
        }
        if (t == 0) {
            out[0] = sh[0] * (1.0f / 33554432.0f);  // mean over 8*16*512*512
            g_count = 0;                            // deterministic replays
        }
    }
}

extern "C" void kernel_launch(void* const* d_in, const int* in_sizes, int n_in,
                              void* d_out, int out_size) {
    const float* X = (const float*)d_in[0];
    opening_kernel<<<NBLK, 128>>>(X, (float*)d_out);
}